// round 4
// baseline (speedup 1.0000x reference)
#include <cuda_runtime.h>
#include <cuda_bf16.h>
#include <cstdint>

// ============================================================================
// out[65536,256] = (x[65536,512] @ W[256,512]^T) * 0.125 + 0.1*bias
// bf16 hi/lo 3-term split + mma.sync.m16n8k16 (base sm_103, no tcgen05).
// x-split is FUSED into the GEMM: fp32 x tiles -> smem -> register convert.
// Only W (tiny) is pre-split into swizzled bf16 tiles.
// ============================================================================

#define KD 512
#define ND 256
#define MROWS 65536
#define BM 128
#define BN 128
#define KB 32                 // k-cols per stage
#define NS 16                 // KD / KB
#define NPIPE 5
#define THREADS 256

#define A_STRIDE 160          // padded fp32 row bytes (128 data + 32 pad)
#define A_BYTES (128 * A_STRIDE)          // 20480
#define BH_BYTES 8192                     // 128 rows * 32 bf16 * 2B
#define STAGE_BYTES (A_BYTES + 2 * BH_BYTES)   // 36864
#define SMEM_TOTAL (NPIPE * STAGE_BYTES)       // 184320

// ---- pre-split W tiles: [stage 16][row 256][32 bf16 = 64B], SW64 swizzled ----
__device__ __align__(1024) unsigned char g_whi[16 * 16384];
__device__ __align__(1024) unsigned char g_wlo[16 * 16384];

// SW64 swizzle: XOR bits[5:4] with bits[8:7] (atom = 8 rows x 64B)
__device__ __forceinline__ uint32_t swz64(uint32_t o) {
    return o ^ ((o >> 3) & 0x30);
}
__device__ __forceinline__ uint32_t smem_u32(const void* p) {
    uint32_t a;
    asm("{ .reg .u64 t; cvta.to.shared.u64 t, %1; cvt.u32.u64 %0, t; }"
        : "=r"(a) : "l"(p));
    return a;
}
__device__ __forceinline__ void cp16(uint32_t saddr, const void* gptr) {
    asm volatile("cp.async.cg.shared.global [%0], [%1], 16;\n"
                 :: "r"(saddr), "l"(gptr));
}
#define CP_COMMIT() asm volatile("cp.async.commit_group;\n" ::: "memory")

__device__ __forceinline__ float2 lds64(uint32_t a) {
    float2 v;
    asm volatile("ld.shared.v2.f32 {%0,%1}, [%2];"
                 : "=f"(v.x), "=f"(v.y) : "r"(a));
    return v;
}
// pack (x -> low half, y -> high half) as bf16x2 (matches A-frag col order)
__device__ __forceinline__ uint32_t packbf(float2 v) {
    uint32_t r;
    asm("cvt.rn.bf16x2.f32 %0, %1, %2;" : "=r"(r) : "f"(v.y), "f"(v.x));
    return r;
}
__device__ __forceinline__ uint32_t lopack(float2 v, uint32_t h) {
    float hx = __uint_as_float(h << 16);
    float hy = __uint_as_float(h & 0xFFFF0000u);
    float2 l;
    l.x = v.x - hx;
    l.y = v.y - hy;
    return packbf(l);
}

#define LDSM4(r, addr) \
    asm volatile("ldmatrix.sync.aligned.m8n8.x4.shared.b16 {%0,%1,%2,%3}, [%4];" \
                 : "=r"((r)[0]), "=r"((r)[1]), "=r"((r)[2]), "=r"((r)[3])  \
                 : "r"(addr))

#define MMA(d, a, b0, b1) \
    asm volatile("mma.sync.aligned.m16n8k16.row.col.f32.bf16.bf16.f32 " \
                 "{%0,%1,%2,%3}, {%4,%5,%6,%7}, {%8,%9}, {%0,%1,%2,%3};" \
                 : "+f"((d)[0]), "+f"((d)[1]), "+f"((d)[2]), "+f"((d)[3]) \
                 : "r"((a)[0]), "r"((a)[1]), "r"((a)[2]), "r"((a)[3]),    \
                   "r"(b0), "r"(b1))

// ============================================================================
// W split: fp32 -> bf16 hi/lo, tile layout [stage][row][64B] with SW64.
// ============================================================================
__global__ void split_w_kernel(const float* __restrict__ src) {
    const int n4 = ND * KD / 4;                       // 32768
    int i = blockIdx.x * blockDim.x + threadIdx.x;
    if (i >= n4) return;
    float4 v = ((const float4*)src)[i];
    int r = i >> 7;                // W row (n index)
    int c4 = i & 127;
    int s = c4 >> 3;               // k-stage
    int cc = c4 & 7;
    int c16 = cc >> 1;
    int sub8 = (cc & 1) * 8;
    size_t tile = (size_t)s * 16384;
    uint32_t off = swz64((uint32_t)(r * 64 + c16 * 16)) + sub8;

    __nv_bfloat16 h0 = __float2bfloat16_rn(v.x);
    __nv_bfloat16 h1 = __float2bfloat16_rn(v.y);
    __nv_bfloat16 h2 = __float2bfloat16_rn(v.z);
    __nv_bfloat16 h3 = __float2bfloat16_rn(v.w);
    __nv_bfloat162 hp0(h0, h1), hp1(h2, h3);
    __nv_bfloat162 lp0(__float2bfloat16_rn(v.x - __bfloat162float(h0)),
                       __float2bfloat16_rn(v.y - __bfloat162float(h1)));
    __nv_bfloat162 lp1(__float2bfloat16_rn(v.z - __bfloat162float(h2)),
                       __float2bfloat16_rn(v.w - __bfloat162float(h3)));
    *(uint2*)(g_whi + tile + off) = make_uint2(*(uint32_t*)&hp0, *(uint32_t*)&hp1);
    *(uint2*)(g_wlo + tile + off) = make_uint2(*(uint32_t*)&lp0, *(uint32_t*)&lp1);
}

// ============================================================================
// Fused GEMM
// ============================================================================
__device__ __forceinline__ void issue_stage(uint32_t sb, const float* x,
                                            int t, int bm, int bn, int tid) {
    const uint32_t buf = sb + (uint32_t)(t % NPIPE) * STAGE_BYTES;
    // A: raw fp32 x tile, 128 rows x 128B, padded smem stride 160B
#pragma unroll
    for (int j = 0; j < 4; j++) {
        int idx = tid + THREADS * j;
        int r = idx >> 3;
        int c = idx & 7;
        const float* src = x + (size_t)(bm + r) * KD + t * KB + c * 4;
        cp16(buf + (uint32_t)(r * A_STRIDE + c * 16), src);
    }
    // B hi/lo: linear copy of pre-swizzled 8KB half-tiles
    const size_t goff = (size_t)t * 16384 + (size_t)bn * 8192;
#pragma unroll
    for (int j = 0; j < 2; j++) {
        int idx = tid + THREADS * j;
        cp16(buf + A_BYTES + (uint32_t)(idx * 16), g_whi + goff + idx * 16);
        cp16(buf + A_BYTES + BH_BYTES + (uint32_t)(idx * 16),
             g_wlo + goff + idx * 16);
    }
}

__global__ void __launch_bounds__(THREADS)
gemm_fused_kernel(const float* __restrict__ x, const float* __restrict__ bias,
                  float* __restrict__ out) {
    extern __shared__ __align__(1024) char smem[];
    const uint32_t sb = smem_u32(smem);
    const int tid = threadIdx.x;
    const int wid = tid >> 5;
    const int lane = tid & 31;
    const int wm = wid >> 2;       // 0..1, warp rows wm*64
    const int wn = wid & 3;        // 0..3, warp cols wn*32
    const int bn = blockIdx.x;     // fastest -> bn pair co-resident (x L2 reuse)
    const int bm = blockIdx.y * BM;

    // prologue: stages 0..NPIPE-2
#pragma unroll
    for (int t = 0; t < NPIPE - 1; t++) {
        issue_stage(sb, x, t, bm, bn, tid);
        CP_COMMIT();
    }

    // per-lane constants
    const int lrow8 = ((lane >> 3) & 1) * 8 + (lane & 7);
    const int lk16 = (lane >> 4) * 16;
    uint32_t boff[2];
#pragma unroll
    for (int g = 0; g < 2; g++)
        boff[g] = (uint32_t)((wn * 32 + g * 16 + lrow8) * 64 + lk16);
    const uint32_t arow = (uint32_t)((wm * 64 + (lane >> 2)) * A_STRIDE
                                     + (lane & 3) * 8);

    float acc[4][4][4];
#pragma unroll
    for (int mi = 0; mi < 4; mi++)
#pragma unroll
        for (int ni = 0; ni < 4; ni++)
#pragma unroll
            for (int j = 0; j < 4; j++) acc[mi][ni][j] = 0.0f;

#pragma unroll 1
    for (int s = 0; s < NS; s++) {
        asm volatile("cp.async.wait_group %0;\n" :: "n"(NPIPE - 2) : "memory");
        __syncthreads();
        {
            const int t = s + NPIPE - 1;
            if (t < NS) issue_stage(sb, x, t, bm, bn, tid);
            CP_COMMIT();
        }
        const uint32_t buf = sb + (uint32_t)(s % NPIPE) * STAGE_BYTES;
        const uint32_t bhi = buf + A_BYTES;
        const uint32_t blo = bhi + BH_BYTES;

#pragma unroll
        for (int ks = 0; ks < 2; ks++) {
            uint32_t bht[2][4], blt[2][4];
#pragma unroll
            for (int g = 0; g < 2; g++)
                LDSM4(bht[g], bhi + swz64(boff[g] + ks * 32));
#pragma unroll
            for (int g = 0; g < 2; g++)
                LDSM4(blt[g], blo + swz64(boff[g] + ks * 32));

#pragma unroll
            for (int mi = 0; mi < 4; mi++) {
                const uint32_t ab = buf + arow + (uint32_t)(mi * 16 * A_STRIDE)
                                  + (uint32_t)(ks * 64);
                float2 v00 = lds64(ab);
                float2 v10 = lds64(ab + 8 * A_STRIDE);
                float2 v01 = lds64(ab + 32);
                float2 v11 = lds64(ab + 8 * A_STRIDE + 32);
                uint32_t ah[4], al[4];
                ah[0] = packbf(v00);
                ah[1] = packbf(v10);
                ah[2] = packbf(v01);
                ah[3] = packbf(v11);
                al[0] = lopack(v00, ah[0]);
                al[1] = lopack(v10, ah[1]);
                al[2] = lopack(v01, ah[2]);
                al[3] = lopack(v11, ah[3]);
#pragma unroll
                for (int g = 0; g < 2; g++) {
                    MMA(acc[mi][2 * g],     ah, bht[g][0], bht[g][2]);
                    MMA(acc[mi][2 * g + 1], ah, bht[g][1], bht[g][3]);
                    MMA(acc[mi][2 * g],     ah, blt[g][0], blt[g][2]);
                    MMA(acc[mi][2 * g + 1], ah, blt[g][1], blt[g][3]);
                    MMA(acc[mi][2 * g],     al, bht[g][0], bht[g][2]);
                    MMA(acc[mi][2 * g + 1], al, bht[g][1], bht[g][3]);
                }
            }
        }
    }

    // ---- epilogue ----
    const int quad = lane >> 2;
    const int tq = lane & 3;
    const float scale = 0.125f;
#pragma unroll
    for (int mi = 0; mi < 4; mi++) {
        const int row0 = bm + wm * 64 + mi * 16 + quad;
#pragma unroll
        for (int ni = 0; ni < 4; ni++) {
            const int col = bn * BN + wn * 32 + ni * 8 + tq * 2;
            const float2 bv = *(const float2*)(bias + col);
            float2 o0, o1;
            o0.x = acc[mi][ni][0] * scale + 0.1f * bv.x;
            o0.y = acc[mi][ni][1] * scale + 0.1f * bv.y;
            o1.x = acc[mi][ni][2] * scale + 0.1f * bv.x;
            o1.y = acc[mi][ni][3] * scale + 0.1f * bv.y;
            *(float2*)(out + (size_t)row0 * ND + col) = o0;
            *(float2*)(out + (size_t)(row0 + 8) * ND + col) = o1;
        }
    }
}

// ============================================================================
extern "C" void kernel_launch(void* const* d_in, const int* in_sizes, int n_in,
                              void* d_out, int out_size) {
    const float* x      = (const float*)d_in[0];   // [65536, 512]
    const float* weight = (const float*)d_in[1];   // [256, 512]
    const float* bias   = (const float*)d_in[2];   // [256]
    float* out = (float*)d_out;                    // [65536, 256]

    cudaFuncSetAttribute(gemm_fused_kernel,
                         cudaFuncAttributeMaxDynamicSharedMemorySize, SMEM_TOTAL);

    split_w_kernel<<<128, 256>>>(weight);
    dim3 grid(ND / BN, MROWS / BM);   // (2, 512), bn fastest
    gemm_fused_kernel<<<grid, THREADS, SMEM_TOTAL>>>(x, bias, out);
}

// round 5
// speedup vs baseline: 1.1623x; 1.1623x over previous
#include <cuda_runtime.h>
#include <cuda_bf16.h>
#include <cstdint>

// ============================================================================
// out[65536,256] = (x[65536,512] @ W[256,512]^T) * 0.125 + 0.1*bias
// bf16 hi/lo 3-term split + mma.sync.m16n8k16 (base sm_103, no tcgen05).
// x-split fused into GEMM (fp32 smem -> register convert).
// R5: NPIPE 5->3 + __launch_bounds__(256,2) => 2 CTAs/SM (16 warps/SM),
// covering per-stage latency bubbles; tensor 45% -> ~85% predicted.
// ============================================================================

#define KD 512
#define ND 256
#define MROWS 65536
#define BM 128
#define BN 128
#define KB 32                 // k-cols per stage
#define NS 16                 // KD / KB
#define NPIPE 3
#define THREADS 256

#define A_STRIDE 160          // padded fp32 row bytes (128 data + 32 pad)
#define A_BYTES (128 * A_STRIDE)          // 20480
#define BH_BYTES 8192                     // 128 rows * 32 bf16 * 2B
#define STAGE_BYTES (A_BYTES + 2 * BH_BYTES)   // 36864
#define SMEM_TOTAL (NPIPE * STAGE_BYTES)       // 110592 -> 2 CTAs/SM

// ---- pre-split W tiles: [stage 16][row 256][32 bf16 = 64B], SW64 swizzled ----
__device__ __align__(1024) unsigned char g_whi[16 * 16384];
__device__ __align__(1024) unsigned char g_wlo[16 * 16384];

// SW64 swizzle: XOR bits[5:4] with bits[8:7] (atom = 8 rows x 64B)
__device__ __forceinline__ uint32_t swz64(uint32_t o) {
    return o ^ ((o >> 3) & 0x30);
}
__device__ __forceinline__ uint32_t smem_u32(const void* p) {
    uint32_t a;
    asm("{ .reg .u64 t; cvta.to.shared.u64 t, %1; cvt.u32.u64 %0, t; }"
        : "=r"(a) : "l"(p));
    return a;
}
__device__ __forceinline__ void cp16(uint32_t saddr, const void* gptr) {
    asm volatile("cp.async.cg.shared.global [%0], [%1], 16;\n"
                 :: "r"(saddr), "l"(gptr));
}
#define CP_COMMIT() asm volatile("cp.async.commit_group;\n" ::: "memory")

__device__ __forceinline__ float2 lds64(uint32_t a) {
    float2 v;
    asm volatile("ld.shared.v2.f32 {%0,%1}, [%2];"
                 : "=f"(v.x), "=f"(v.y) : "r"(a));
    return v;
}
// pack (x -> low half, y -> high half) as bf16x2 (matches A-frag col order)
__device__ __forceinline__ uint32_t packbf(float2 v) {
    uint32_t r;
    asm("cvt.rn.bf16x2.f32 %0, %1, %2;" : "=r"(r) : "f"(v.y), "f"(v.x));
    return r;
}
__device__ __forceinline__ uint32_t lopack(float2 v, uint32_t h) {
    float hx = __uint_as_float(h << 16);
    float hy = __uint_as_float(h & 0xFFFF0000u);
    float2 l;
    l.x = v.x - hx;
    l.y = v.y - hy;
    return packbf(l);
}

#define LDSM4(r, addr) \
    asm volatile("ldmatrix.sync.aligned.m8n8.x4.shared.b16 {%0,%1,%2,%3}, [%4];" \
                 : "=r"((r)[0]), "=r"((r)[1]), "=r"((r)[2]), "=r"((r)[3])  \
                 : "r"(addr))

#define MMA(d, a, b0, b1) \
    asm volatile("mma.sync.aligned.m16n8k16.row.col.f32.bf16.bf16.f32 " \
                 "{%0,%1,%2,%3}, {%4,%5,%6,%7}, {%8,%9}, {%0,%1,%2,%3};" \
                 : "+f"((d)[0]), "+f"((d)[1]), "+f"((d)[2]), "+f"((d)[3]) \
                 : "r"((a)[0]), "r"((a)[1]), "r"((a)[2]), "r"((a)[3]),    \
                   "r"(b0), "r"(b1))

// ============================================================================
// W split: fp32 -> bf16 hi/lo, tile layout [stage][row][64B] with SW64.
// ============================================================================
__global__ void split_w_kernel(const float* __restrict__ src) {
    const int n4 = ND * KD / 4;                       // 32768
    int i = blockIdx.x * blockDim.x + threadIdx.x;
    if (i >= n4) return;
    float4 v = ((const float4*)src)[i];
    int r = i >> 7;                // W row (n index)
    int c4 = i & 127;
    int s = c4 >> 3;               // k-stage
    int cc = c4 & 7;
    int c16 = cc >> 1;
    int sub8 = (cc & 1) * 8;
    size_t tile = (size_t)s * 16384;
    uint32_t off = swz64((uint32_t)(r * 64 + c16 * 16)) + sub8;

    __nv_bfloat16 h0 = __float2bfloat16_rn(v.x);
    __nv_bfloat16 h1 = __float2bfloat16_rn(v.y);
    __nv_bfloat16 h2 = __float2bfloat16_rn(v.z);
    __nv_bfloat16 h3 = __float2bfloat16_rn(v.w);
    __nv_bfloat162 hp0(h0, h1), hp1(h2, h3);
    __nv_bfloat162 lp0(__float2bfloat16_rn(v.x - __bfloat162float(h0)),
                       __float2bfloat16_rn(v.y - __bfloat162float(h1)));
    __nv_bfloat162 lp1(__float2bfloat16_rn(v.z - __bfloat162float(h2)),
                       __float2bfloat16_rn(v.w - __bfloat162float(h3)));
    *(uint2*)(g_whi + tile + off) = make_uint2(*(uint32_t*)&hp0, *(uint32_t*)&hp1);
    *(uint2*)(g_wlo + tile + off) = make_uint2(*(uint32_t*)&lp0, *(uint32_t*)&lp1);
}

// ============================================================================
// Fused GEMM
// ============================================================================
__device__ __forceinline__ void issue_stage(uint32_t sb, const float* x,
                                            int t, int bm, int bn, int tid) {
    const uint32_t buf = sb + (uint32_t)(t % NPIPE) * STAGE_BYTES;
    // A: raw fp32 x tile, 128 rows x 128B, padded smem stride 160B
#pragma unroll
    for (int j = 0; j < 4; j++) {
        int idx = tid + THREADS * j;
        int r = idx >> 3;
        int c = idx & 7;
        const float* src = x + (size_t)(bm + r) * KD + t * KB + c * 4;
        cp16(buf + (uint32_t)(r * A_STRIDE + c * 16), src);
    }
    // B hi/lo: linear copy of pre-swizzled 8KB half-tiles
    const size_t goff = (size_t)t * 16384 + (size_t)bn * 8192;
#pragma unroll
    for (int j = 0; j < 2; j++) {
        int idx = tid + THREADS * j;
        cp16(buf + A_BYTES + (uint32_t)(idx * 16), g_whi + goff + idx * 16);
        cp16(buf + A_BYTES + BH_BYTES + (uint32_t)(idx * 16),
             g_wlo + goff + idx * 16);
    }
}

__global__ void __launch_bounds__(THREADS, 2)
gemm_fused_kernel(const float* __restrict__ x, const float* __restrict__ bias,
                  float* __restrict__ out) {
    extern __shared__ __align__(1024) char smem[];
    const uint32_t sb = smem_u32(smem);
    const int tid = threadIdx.x;
    const int wid = tid >> 5;
    const int lane = tid & 31;
    const int wm = wid >> 2;       // 0..1, warp rows wm*64
    const int wn = wid & 3;        // 0..3, warp cols wn*32
    const int bn = blockIdx.x;     // fastest -> bn pair co-resident (x L2 reuse)
    const int bm = blockIdx.y * BM;

    // prologue: stages 0..NPIPE-2
#pragma unroll
    for (int t = 0; t < NPIPE - 1; t++) {
        issue_stage(sb, x, t, bm, bn, tid);
        CP_COMMIT();
    }

    // per-lane constants
    const int lrow8 = ((lane >> 3) & 1) * 8 + (lane & 7);
    const int lk16 = (lane >> 4) * 16;
    uint32_t boff[2];
#pragma unroll
    for (int g = 0; g < 2; g++)
        boff[g] = (uint32_t)((wn * 32 + g * 16 + lrow8) * 64 + lk16);
    const uint32_t arow = (uint32_t)((wm * 64 + (lane >> 2)) * A_STRIDE
                                     + (lane & 3) * 8);

    float acc[4][4][4];
#pragma unroll
    for (int mi = 0; mi < 4; mi++)
#pragma unroll
        for (int ni = 0; ni < 4; ni++)
#pragma unroll
            for (int j = 0; j < 4; j++) acc[mi][ni][j] = 0.0f;

#pragma unroll 1
    for (int s = 0; s < NS; s++) {
        asm volatile("cp.async.wait_group %0;\n" :: "n"(NPIPE - 2) : "memory");
        __syncthreads();
        {
            const int t = s + NPIPE - 1;
            if (t < NS) issue_stage(sb, x, t, bm, bn, tid);
            CP_COMMIT();
        }
        const uint32_t buf = sb + (uint32_t)(s % NPIPE) * STAGE_BYTES;
        const uint32_t bhi = buf + A_BYTES;
        const uint32_t blo = bhi + BH_BYTES;

#pragma unroll
        for (int ks = 0; ks < 2; ks++) {
            uint32_t bht[2][4], blt[2][4];
#pragma unroll
            for (int g = 0; g < 2; g++)
                LDSM4(bht[g], bhi + swz64(boff[g] + ks * 32));
#pragma unroll
            for (int g = 0; g < 2; g++)
                LDSM4(blt[g], blo + swz64(boff[g] + ks * 32));

#pragma unroll
            for (int mi = 0; mi < 4; mi++) {
                const uint32_t ab = buf + arow + (uint32_t)(mi * 16 * A_STRIDE)
                                  + (uint32_t)(ks * 64);
                float2 v00 = lds64(ab);
                float2 v10 = lds64(ab + 8 * A_STRIDE);
                float2 v01 = lds64(ab + 32);
                float2 v11 = lds64(ab + 8 * A_STRIDE + 32);
                uint32_t ah[4], al[4];
                ah[0] = packbf(v00);
                ah[1] = packbf(v10);
                ah[2] = packbf(v01);
                ah[3] = packbf(v11);
                al[0] = lopack(v00, ah[0]);
                al[1] = lopack(v10, ah[1]);
                al[2] = lopack(v01, ah[2]);
                al[3] = lopack(v11, ah[3]);
#pragma unroll
                for (int g = 0; g < 2; g++) {
                    MMA(acc[mi][2 * g],     ah, bht[g][0], bht[g][2]);
                    MMA(acc[mi][2 * g + 1], ah, bht[g][1], bht[g][3]);
                    MMA(acc[mi][2 * g],     ah, blt[g][0], blt[g][2]);
                    MMA(acc[mi][2 * g + 1], ah, blt[g][1], blt[g][3]);
                    MMA(acc[mi][2 * g],     al, bht[g][0], bht[g][2]);
                    MMA(acc[mi][2 * g + 1], al, bht[g][1], bht[g][3]);
                }
            }
        }
    }

    // ---- epilogue ----
    const int quad = lane >> 2;
    const int tq = lane & 3;
    const float scale = 0.125f;
#pragma unroll
    for (int mi = 0; mi < 4; mi++) {
        const int row0 = bm + wm * 64 + mi * 16 + quad;
#pragma unroll
        for (int ni = 0; ni < 4; ni++) {
            const int col = bn * BN + wn * 32 + ni * 8 + tq * 2;
            const float2 bv = *(const float2*)(bias + col);
            float2 o0, o1;
            o0.x = acc[mi][ni][0] * scale + 0.1f * bv.x;
            o0.y = acc[mi][ni][1] * scale + 0.1f * bv.y;
            o1.x = acc[mi][ni][2] * scale + 0.1f * bv.x;
            o1.y = acc[mi][ni][3] * scale + 0.1f * bv.y;
            *(float2*)(out + (size_t)row0 * ND + col) = o0;
            *(float2*)(out + (size_t)(row0 + 8) * ND + col) = o1;
        }
    }
}

// ============================================================================
extern "C" void kernel_launch(void* const* d_in, const int* in_sizes, int n_in,
                              void* d_out, int out_size) {
    const float* x      = (const float*)d_in[0];   // [65536, 512]
    const float* weight = (const float*)d_in[1];   // [256, 512]
    const float* bias   = (const float*)d_in[2];   // [256]
    float* out = (float*)d_out;                    // [65536, 256]

    cudaFuncSetAttribute(gemm_fused_kernel,
                         cudaFuncAttributeMaxDynamicSharedMemorySize, SMEM_TOTAL);

    split_w_kernel<<<128, 256>>>(weight);
    dim3 grid(ND / BN, MROWS / BM);   // (2, 512), bn fastest
    gemm_fused_kernel<<<grid, THREADS, SMEM_TOTAL>>>(x, bias, out);
}

// round 6
// speedup vs baseline: 1.2046x; 1.0363x over previous
#include <cuda_runtime.h>
#include <cuda_bf16.h>
#include <cstdint>

// ============================================================================
// out[65536,256] = (x[65536,512] @ W[256,512]^T) * 0.125 + 0.1*bias
// bf16 hi/lo 3-term split + mma.sync.m16n8k16 (base sm_103, no tcgen05).
// R6: cooperative in-CTA conversion (fp32 smem -> bf16 hi/lo smem, once per
// CTA) + all-ldmatrix consumer. NPIPE=2, 2 CTAs/SM.
// ============================================================================

#define KD 512
#define ND 256
#define MROWS 65536
#define BM 128
#define BN 128
#define KB 32                 // k-cols per stage
#define NS 16                 // KD / KB
#define THREADS 256

#define A_STRIDE 160                      // padded fp32 row bytes
#define AF_BYTES (128 * A_STRIDE)         // 20480
#define T_BYTES 8192                      // one bf16 tile: 128 rows * 64B
// stage: AF32 | AHI | ALO | BHI | BLO
#define AHI_OFF AF_BYTES
#define ALO_OFF (AF_BYTES + T_BYTES)
#define BHI_OFF (AF_BYTES + 2 * T_BYTES)
#define BLO_OFF (AF_BYTES + 3 * T_BYTES)
#define STAGE_BYTES (AF_BYTES + 4 * T_BYTES)   // 53248
#define SMEM_TOTAL (2 * STAGE_BYTES)           // 106496 -> 2 CTAs/SM

// ---- pre-split W tiles: [stage 16][row 256][32 bf16 = 64B], SW64 swizzled ----
__device__ __align__(1024) unsigned char g_whi[16 * 16384];
__device__ __align__(1024) unsigned char g_wlo[16 * 16384];

__device__ __forceinline__ uint32_t swz64(uint32_t o) {
    return o ^ ((o >> 3) & 0x30);
}
__device__ __forceinline__ uint32_t smem_u32(const void* p) {
    uint32_t a;
    asm("{ .reg .u64 t; cvta.to.shared.u64 t, %1; cvt.u32.u64 %0, t; }"
        : "=r"(a) : "l"(p));
    return a;
}
__device__ __forceinline__ void cp16(uint32_t saddr, const void* gptr) {
    asm volatile("cp.async.cg.shared.global [%0], [%1], 16;\n"
                 :: "r"(saddr), "l"(gptr));
}
#define CP_COMMIT() asm volatile("cp.async.commit_group;\n" ::: "memory")

__device__ __forceinline__ float4 lds128(uint32_t a) {
    float4 v;
    asm volatile("ld.shared.v4.f32 {%0,%1,%2,%3}, [%4];"
                 : "=f"(v.x), "=f"(v.y), "=f"(v.z), "=f"(v.w) : "r"(a));
    return v;
}
__device__ __forceinline__ void sts64(uint32_t a, uint32_t r0, uint32_t r1) {
    asm volatile("st.shared.v2.b32 [%0], {%1,%2};" :: "r"(a), "r"(r0), "r"(r1)
                 : "memory");
}
// pack (x -> low half, y -> high half) as bf16x2
__device__ __forceinline__ uint32_t packbf(float lo, float hi) {
    uint32_t r;
    asm("cvt.rn.bf16x2.f32 %0, %1, %2;" : "=r"(r) : "f"(hi), "f"(lo));
    return r;
}

#define LDSM4(r, addr) \
    asm volatile("ldmatrix.sync.aligned.m8n8.x4.shared.b16 {%0,%1,%2,%3}, [%4];" \
                 : "=r"((r)[0]), "=r"((r)[1]), "=r"((r)[2]), "=r"((r)[3])  \
                 : "r"(addr))

#define MMA(d, a, b0, b1) \
    asm volatile("mma.sync.aligned.m16n8k16.row.col.f32.bf16.bf16.f32 " \
                 "{%0,%1,%2,%3}, {%4,%5,%6,%7}, {%8,%9}, {%0,%1,%2,%3};" \
                 : "+f"((d)[0]), "+f"((d)[1]), "+f"((d)[2]), "+f"((d)[3]) \
                 : "r"((a)[0]), "r"((a)[1]), "r"((a)[2]), "r"((a)[3]),    \
                   "r"(b0), "r"(b1))

// ============================================================================
// W split: fp32 -> bf16 hi/lo, tile layout [stage][row][64B] with SW64.
// ============================================================================
__global__ void split_w_kernel(const float* __restrict__ src) {
    const int n4 = ND * KD / 4;                       // 32768
    int i = blockIdx.x * blockDim.x + threadIdx.x;
    if (i >= n4) return;
    float4 v = ((const float4*)src)[i];
    int r = i >> 7;                // W row (n index)
    int c4 = i & 127;
    int s = c4 >> 3;               // k-stage
    int cc = c4 & 7;
    size_t tile = (size_t)s * 16384;
    uint32_t off = swz64((uint32_t)(r * 64 + cc * 8));

    uint32_t h01 = packbf(v.x, v.y);
    uint32_t h23 = packbf(v.z, v.w);
    float lx = v.x - __uint_as_float(h01 << 16);
    float ly = v.y - __uint_as_float(h01 & 0xFFFF0000u);
    float lz = v.z - __uint_as_float(h23 << 16);
    float lw = v.w - __uint_as_float(h23 & 0xFFFF0000u);
    *(uint2*)(g_whi + tile + off) = make_uint2(h01, h23);
    *(uint2*)(g_wlo + tile + off) = make_uint2(packbf(lx, ly), packbf(lz, lw));
}

// ============================================================================
// Fused GEMM
// ============================================================================
__device__ __forceinline__ void issue_stage(uint32_t sb, const float* x,
                                            int t, int bm, int bn, int tid) {
    const uint32_t buf = sb + (uint32_t)(t & 1) * STAGE_BYTES;
    // A: raw fp32 x tile, 128 rows x 128B, smem stride 160B
#pragma unroll
    for (int j = 0; j < 4; j++) {
        int idx = tid + THREADS * j;
        int r = idx >> 3;
        int c = idx & 7;
        const float* src = x + (size_t)(bm + r) * KD + t * KB + c * 4;
        cp16(buf + (uint32_t)(r * A_STRIDE + c * 16), src);
    }
    // B hi/lo: linear copy of pre-swizzled 8KB half-tiles
    const size_t goff = (size_t)t * 16384 + (size_t)bn * 8192;
#pragma unroll
    for (int j = 0; j < 2; j++) {
        int idx = tid + THREADS * j;
        cp16(buf + BHI_OFF + (uint32_t)(idx * 16), g_whi + goff + idx * 16);
        cp16(buf + BLO_OFF + (uint32_t)(idx * 16), g_wlo + goff + idx * 16);
    }
    CP_COMMIT();
}

__global__ void __launch_bounds__(THREADS, 2)
gemm_fused_kernel(const float* __restrict__ x, const float* __restrict__ bias,
                  float* __restrict__ out) {
    extern __shared__ __align__(1024) char smem[];
    const uint32_t sb = smem_u32(smem);
    const int tid = threadIdx.x;
    const int wid = tid >> 5;
    const int lane = tid & 31;
    const int wm = wid >> 2;       // 0..1, warp rows wm*64
    const int wn = wid & 3;        // 0..3, warp cols wn*32
    const int bn = blockIdx.x;     // fastest: bn pair co-resident (x L2 reuse)
    const int bm = blockIdx.y * BM;

    // prologue: stage 0
    issue_stage(sb, x, 0, bm, bn, tid);

    // per-lane ldmatrix constants (R3-proven fragment math)
    const int lrow8 = ((lane >> 3) & 1) * 8 + (lane & 7);
    const int lk16 = (lane >> 4) * 16;
    uint32_t aoff[4], boff[2];
#pragma unroll
    for (int mi = 0; mi < 4; mi++)
        aoff[mi] = (uint32_t)((wm * 64 + mi * 16 + lrow8) * 64 + lk16);
#pragma unroll
    for (int g = 0; g < 2; g++)
        boff[g] = (uint32_t)((wn * 32 + g * 16 + lrow8) * 64 + lk16);

    // conversion mapping: 4 float4 per thread
    const int cr = tid >> 3;        // row 0..31 (+32*j... see loop)
    const int ccol = tid & 7;       // float4 col

    float acc[4][4][4];
#pragma unroll
    for (int mi = 0; mi < 4; mi++)
#pragma unroll
        for (int ni = 0; ni < 4; ni++)
#pragma unroll
            for (int j = 0; j < 4; j++) acc[mi][ni][j] = 0.0f;

#pragma unroll 1
    for (int s = 0; s < NS; s++) {
        asm volatile("cp.async.wait_group 0;\n" ::: "memory");
        __syncthreads();               // stage s arrived; stage s-1 fully read

        if (s + 1 < NS) issue_stage(sb, x, s + 1, bm, bn, tid);

        const uint32_t buf = sb + (uint32_t)(s & 1) * STAGE_BYTES;

        // ---- cooperative convert: fp32 A -> bf16 hi/lo tiles ----
#pragma unroll
        for (int j = 0; j < 4; j++) {
            const int r = cr + 32 * j;
            float4 v = lds128(buf + (uint32_t)(r * A_STRIDE + ccol * 16));
            uint32_t h01 = packbf(v.x, v.y);
            uint32_t h23 = packbf(v.z, v.w);
            float lx = v.x - __uint_as_float(h01 << 16);
            float ly = v.y - __uint_as_float(h01 & 0xFFFF0000u);
            float lz = v.z - __uint_as_float(h23 << 16);
            float lw = v.w - __uint_as_float(h23 & 0xFFFF0000u);
            uint32_t daddr = swz64((uint32_t)(r * 64 + ccol * 8));
            sts64(buf + AHI_OFF + daddr, h01, h23);
            sts64(buf + ALO_OFF + daddr, packbf(lx, ly), packbf(lz, lw));
        }
        __syncthreads();               // converted tiles visible

        // ---- consumer: all-ldmatrix ----
#pragma unroll
        for (int ks = 0; ks < 2; ks++) {
            const uint32_t kadd = (uint32_t)(ks * 32);
            uint32_t bht[2][4], blt[2][4];
#pragma unroll
            for (int g = 0; g < 2; g++) {
                LDSM4(bht[g], buf + BHI_OFF + swz64(boff[g] + kadd));
                LDSM4(blt[g], buf + BLO_OFF + swz64(boff[g] + kadd));
            }
#pragma unroll
            for (int mi = 0; mi < 4; mi++) {
                uint32_t ah[4], al[4];
                LDSM4(ah, buf + AHI_OFF + swz64(aoff[mi] + kadd));
                LDSM4(al, buf + ALO_OFF + swz64(aoff[mi] + kadd));
#pragma unroll
                for (int g = 0; g < 2; g++) {
                    MMA(acc[mi][2 * g],     ah, bht[g][0], bht[g][2]);
                    MMA(acc[mi][2 * g + 1], ah, bht[g][1], bht[g][3]);
                    MMA(acc[mi][2 * g],     ah, blt[g][0], blt[g][2]);
                    MMA(acc[mi][2 * g + 1], ah, blt[g][1], blt[g][3]);
                    MMA(acc[mi][2 * g],     al, bht[g][0], bht[g][2]);
                    MMA(acc[mi][2 * g + 1], al, bht[g][1], bht[g][3]);
                }
            }
        }
    }

    // ---- epilogue ----
    const int quad = lane >> 2;
    const int tq = lane & 3;
    const float scale = 0.125f;
#pragma unroll
    for (int mi = 0; mi < 4; mi++) {
        const int row0 = bm + wm * 64 + mi * 16 + quad;
#pragma unroll
        for (int ni = 0; ni < 4; ni++) {
            const int col = bn * BN + wn * 32 + ni * 8 + tq * 2;
            const float2 bv = *(const float2*)(bias + col);
            float2 o0, o1;
            o0.x = acc[mi][ni][0] * scale + 0.1f * bv.x;
            o0.y = acc[mi][ni][1] * scale + 0.1f * bv.y;
            o1.x = acc[mi][ni][2] * scale + 0.1f * bv.x;
            o1.y = acc[mi][ni][3] * scale + 0.1f * bv.y;
            *(float2*)(out + (size_t)row0 * ND + col) = o0;
            *(float2*)(out + (size_t)(row0 + 8) * ND + col) = o1;
        }
    }
}

// ============================================================================
extern "C" void kernel_launch(void* const* d_in, const int* in_sizes, int n_in,
                              void* d_out, int out_size) {
    const float* x      = (const float*)d_in[0];   // [65536, 512]
    const float* weight = (const float*)d_in[1];   // [256, 512]
    const float* bias   = (const float*)d_in[2];   // [256]
    float* out = (float*)d_out;                    // [65536, 256]

    cudaFuncSetAttribute(gemm_fused_kernel,
                         cudaFuncAttributeMaxDynamicSharedMemorySize, SMEM_TOTAL);

    split_w_kernel<<<128, 256>>>(weight);
    dim3 grid(ND / BN, MROWS / BM);   // (2, 512), bn fastest
    gemm_fused_kernel<<<grid, THREADS, SMEM_TOTAL>>>(x, bias, out);
}